// round 3
// baseline (speedup 1.0000x reference)
#include <cuda_runtime.h>
#include <cstdint>

#define NEG_INF_F (-1e9f)
#define HTHRESH_F (-1e8f)

// B=8, S=512, D=1024, H=16, DK=64
#define BB 8
#define SS 512
#define DD 1024
#define HH 16
#define DK 64
#define MTOT (BB*SS)          // 4096
#define BHTOT (BB*HH)         // 128

// -------- scratch (device globals; no cudaMalloc allowed) --------
__device__ float g_q[BB*HH*SS*DK];
__device__ float g_k[BB*HH*SS*DK];
__device__ float g_v[BB*HH*SS*DK];
__device__ float g_ctx[MTOT*DD];
__device__ float g_res[MTOT*DD];

// -------- helpers --------
__device__ __forceinline__ unsigned f2tf(float f) {
    unsigned u;
    asm("cvt.rna.tf32.f32 %0, %1;" : "=r"(u) : "f"(f));
    return u;
}
__device__ __forceinline__ float tf2f(float f) {  // round to tf32, keep as float bits
    return __uint_as_float(f2tf(f));
}
__device__ __forceinline__ void mma8(float c[4], const unsigned a[4], unsigned b0, unsigned b1) {
    asm volatile(
        "mma.sync.aligned.m16n8k8.row.col.f32.tf32.tf32.f32 "
        "{%0,%1,%2,%3}, {%4,%5,%6,%7}, {%8,%9}, {%0,%1,%2,%3};\n"
        : "+f"(c[0]), "+f"(c[1]), "+f"(c[2]), "+f"(c[3])
        : "r"(a[0]), "r"(a[1]), "r"(a[2]), "r"(a[3]), "r"(b0), "r"(b1));
}

// =====================================================================
// GEMM: C[M=4096, N=1024] = A @ W (+bias [+residual])
// MODE 0: QKV projection, z in {0,1,2} picks Wq/Wk/Wv, epilogue scatters
//         to [B,H,S,DK] layout in g_q/g_k/g_v.
// MODE 1: out-proj: A = g_ctx, adds bias + residual x, writes g_res.
// Tiles: BM=128, BN=64, BK=32; 256 threads = 8 warps (4M x 2N), warp 32x32.
// =====================================================================
template<int MODE>
__global__ __launch_bounds__(256)
void gemm_tf32_kernel(const float* __restrict__ Aparam,
                      const float* __restrict__ W0, const float* __restrict__ W1,
                      const float* __restrict__ W2,
                      const float* __restrict__ bias0, const float* __restrict__ bias1,
                      const float* __restrict__ bias2,
                      const float* __restrict__ xres)
{
    __shared__ float sA[128 * 40];   // stride 40: conflict-free frag reads
    __shared__ float sB[32 * 72];    // stride 72

    const int z = blockIdx.z;
    const float* W    = (z == 0) ? W0 : (z == 1 ? W1 : W2);
    const float* bias = (z == 0) ? bias0 : (z == 1 ? bias1 : bias2);
    const float* A    = (MODE == 0) ? Aparam : g_ctx;
    float* dst;
    if (MODE == 0) dst = (z == 0) ? g_q : (z == 1 ? g_k : g_v);
    else           dst = g_res;

    const int m0 = blockIdx.x * 128;
    const int n0 = blockIdx.y * 64;
    const int tid = threadIdx.x;
    const int warp = tid >> 5, lane = tid & 31, gid = lane >> 2, tig = lane & 3;
    const int wm = warp & 3, wn = warp >> 2;   // 4 x 2 warp grid

    float acc[2][4][4];
    #pragma unroll
    for (int i = 0; i < 2; i++)
        #pragma unroll
        for (int j = 0; j < 4; j++)
            #pragma unroll
            for (int k = 0; k < 4; k++) acc[i][j][k] = 0.f;

    for (int kt = 0; kt < DD; kt += 32) {
        __syncthreads();
        // load A tile: 128 rows x 32 cols = 1024 float4
        #pragma unroll
        for (int it = 0; it < 4; it++) {
            int f = tid + 256 * it;
            int r = f >> 3, c = (f & 7) << 2;
            float4 v = *reinterpret_cast<const float4*>(A + (size_t)(m0 + r) * DD + kt + c);
            float* p = &sA[r * 40 + c];
            p[0] = tf2f(v.x); p[1] = tf2f(v.y); p[2] = tf2f(v.z); p[3] = tf2f(v.w);
        }
        // load B tile: 32 rows x 64 cols = 512 float4
        #pragma unroll
        for (int it = 0; it < 2; it++) {
            int f = tid + 256 * it;
            int r = f >> 4, c = (f & 15) << 2;
            float4 v = *reinterpret_cast<const float4*>(W + (size_t)(kt + r) * DD + n0 + c);
            float* p = &sB[r * 72 + c];
            p[0] = tf2f(v.x); p[1] = tf2f(v.y); p[2] = tf2f(v.z); p[3] = tf2f(v.w);
        }
        __syncthreads();

        #pragma unroll
        for (int ks = 0; ks < 4; ks++) {
            const int kk = ks * 8;
            unsigned a[2][4];
            #pragma unroll
            for (int mf = 0; mf < 2; mf++) {
                int rb = wm * 32 + mf * 16 + gid;
                a[mf][0] = __float_as_uint(sA[rb * 40 + kk + tig]);
                a[mf][1] = __float_as_uint(sA[(rb + 8) * 40 + kk + tig]);
                a[mf][2] = __float_as_uint(sA[rb * 40 + kk + 4 + tig]);
                a[mf][3] = __float_as_uint(sA[(rb + 8) * 40 + kk + 4 + tig]);
            }
            #pragma unroll
            for (int nf = 0; nf < 4; nf++) {
                int nb = wn * 32 + nf * 8 + gid;
                unsigned bb0 = __float_as_uint(sB[(kk + tig) * 72 + nb]);
                unsigned bb1 = __float_as_uint(sB[(kk + 4 + tig) * 72 + nb]);
                mma8(acc[0][nf], a[0], bb0, bb1);
                mma8(acc[1][nf], a[1], bb0, bb1);
            }
        }
    }

    // epilogue
    #pragma unroll
    for (int mf = 0; mf < 2; mf++) {
        #pragma unroll
        for (int rr = 0; rr < 2; rr++) {
            int m = m0 + wm * 32 + mf * 16 + gid + rr * 8;
            #pragma unroll
            for (int nf = 0; nf < 4; nf++) {
                int n = n0 + wn * 32 + nf * 8 + tig * 2;
                float v0 = acc[mf][nf][rr * 2 + 0] + bias[n];
                float v1 = acc[mf][nf][rr * 2 + 1] + bias[n + 1];
                if (MODE == 0) {
                    int bidx = m >> 9, s = m & 511, hh = n >> 6, d = n & 63;
                    *reinterpret_cast<float2*>(
                        &dst[(((size_t)bidx * HH + hh) * SS + s) * DK + d]) = make_float2(v0, v1);
                } else {
                    v0 += xres[(size_t)m * DD + n];
                    v1 += xres[(size_t)m * DD + n + 1];
                    *reinterpret_cast<float2*>(&dst[(size_t)m * DD + n]) = make_float2(v0, v1);
                }
            }
        }
    }
}

// =====================================================================
// Fused attention kernel: block = (b,h, 64-row q-tile), 256 threads.
//   phase1: S = Q @ K^T * 0.125, masked + help-blended (K fully in smem)
//   phase2: row softmax in smem; write attn (fp32) to gmem; keep P (tf32)
//   phase3: ctx = P @ V, V streamed in 64-row chunks
// smem: sK 512x72 floats (reused as scores 64x516), sQV 64x72 floats.
// =====================================================================
#define SMEM_K_FLOATS (512 * 72)
#define SMEM_QV_FLOATS (64 * 72)
#define ATTN_SMEM_BYTES ((SMEM_K_FLOATS + SMEM_QV_FLOATS) * 4)

__global__ __launch_bounds__(256)
void attn_fused_kernel(const float* __restrict__ help_vals,
                       const int* __restrict__ help_mask,
                       const int* __restrict__ amask,
                       float* __restrict__ attn_out)
{
    extern __shared__ float smem[];
    float* sK  = smem;                     // K tile, later scores (stride 516)
    float* sQV = smem + SMEM_K_FLOATS;     // Q tile, later V chunks

    const int bh = blockIdx.x;
    const int b = bh >> 4;
    const int h = bh & 15;
    const int q0 = blockIdx.y * 64;
    const int tid = threadIdx.x;
    const int warp = tid >> 5, lane = tid & 31, gid = lane >> 2, tig = lane & 3;

    // ---- load Q tile (64x64) and full K (512x64), tf32-rounded ----
    {
        const float* qsrc = g_q + ((size_t)bh * SS + q0) * DK;
        #pragma unroll
        for (int it = 0; it < 4; it++) {
            int f = tid + 256 * it;
            int r = f >> 4, c = (f & 15) << 2;
            float4 v = *reinterpret_cast<const float4*>(qsrc + r * DK + c);
            float* p = &sQV[r * 72 + c];
            p[0] = tf2f(v.x); p[1] = tf2f(v.y); p[2] = tf2f(v.z); p[3] = tf2f(v.w);
        }
        const float* ksrc = g_k + (size_t)bh * SS * DK;
        #pragma unroll
        for (int it = 0; it < 32; it++) {
            int f = tid + 256 * it;
            int r = f >> 4, c = (f & 15) << 2;
            float4 v = *reinterpret_cast<const float4*>(ksrc + r * DK + c);
            float* p = &sK[r * 72 + c];
            p[0] = tf2f(v.x); p[1] = tf2f(v.y); p[2] = tf2f(v.z); p[3] = tf2f(v.w);
        }
    }
    __syncthreads();

    // ---- phase 1: scores = Q @ K^T ----
    const int wm = warp & 1;   // 2 warps over M (32 rows each)
    const int wn = warp >> 1;  // 4 warps over N (128 cols each)
    float acc[2][16][4];
    #pragma unroll
    for (int i = 0; i < 2; i++)
        #pragma unroll
        for (int j = 0; j < 16; j++)
            #pragma unroll
            for (int k = 0; k < 4; k++) acc[i][j][k] = 0.f;

    #pragma unroll 1
    for (int kk = 0; kk < DK; kk += 8) {
        unsigned a[2][4];
        #pragma unroll
        for (int mf = 0; mf < 2; mf++) {
            int rb = wm * 32 + mf * 16 + gid;
            a[mf][0] = __float_as_uint(sQV[rb * 72 + kk + tig]);
            a[mf][1] = __float_as_uint(sQV[(rb + 8) * 72 + kk + tig]);
            a[mf][2] = __float_as_uint(sQV[rb * 72 + kk + 4 + tig]);
            a[mf][3] = __float_as_uint(sQV[(rb + 8) * 72 + kk + 4 + tig]);
        }
        #pragma unroll
        for (int nf = 0; nf < 16; nf++) {
            int nb = wn * 128 + nf * 8 + gid;
            unsigned bb0 = __float_as_uint(sK[nb * 72 + kk + tig]);
            unsigned bb1 = __float_as_uint(sK[nb * 72 + kk + 4 + tig]);
            mma8(acc[0][nf], a[0], bb0, bb1);
            mma8(acc[1][nf], a[1], bb0, bb1);
        }
    }
    __syncthreads();   // K no longer needed; overlay scores

    // ---- epilogue: scale + attn_mask + dependency blend -> sK (stride 516) ----
    {
        const float* hvp = help_vals + ((size_t)bh * SS + q0) * SS;
        const int*   hmp = help_mask + ((size_t)bh * SS + q0) * SS;
        const int*   amp = amask + ((size_t)b * SS + q0) * SS;
        #pragma unroll
        for (int mf = 0; mf < 2; mf++) {
            #pragma unroll
            for (int rr = 0; rr < 2; rr++) {
                int lm = wm * 32 + mf * 16 + gid + rr * 8;
                #pragma unroll
                for (int nf = 0; nf < 16; nf++) {
                    int ln = wn * 128 + nf * 8 + tig * 2;
                    size_t off = (size_t)lm * SS + ln;
                    float2 hv2 = *reinterpret_cast<const float2*>(hvp + off);
                    int2   hm2 = *reinterpret_cast<const int2*>(hmp + off);
                    int2   am2 = *reinterpret_cast<const int2*>(amp + off);
                    float s0 = am2.x ? NEG_INF_F : acc[mf][nf][rr * 2 + 0] * 0.125f;
                    float s1 = am2.y ? NEG_INF_F : acc[mf][nf][rr * 2 + 1] * 0.125f;
                    if (hm2.x && hv2.x > HTHRESH_F) s0 = 0.5f * hv2.x + 0.5f * s0;
                    if (hm2.y && hv2.y > HTHRESH_F) s1 = 0.5f * hv2.y + 0.5f * s1;
                    sK[lm * 516 + ln]     = s0;
                    sK[lm * 516 + ln + 1] = s1;
                }
            }
        }
    }
    __syncthreads();

    // ---- phase 2: softmax per row; write attn; store P (tf32) ----
    {
        float* aout = attn_out + ((size_t)bh * SS + q0) * SS;
        #pragma unroll 1
        for (int j = 0; j < 8; j++) {
            int r = warp * 8 + j;
            float* row = &sK[r * 516];
            float vals[16];
            float mx = -3e38f;
            #pragma unroll
            for (int i = 0; i < 16; i++) { vals[i] = row[lane + 32 * i]; mx = fmaxf(mx, vals[i]); }
            #pragma unroll
            for (int o = 16; o > 0; o >>= 1) mx = fmaxf(mx, __shfl_xor_sync(0xffffffffu, mx, o));
            float sum = 0.f;
            #pragma unroll
            for (int i = 0; i < 16; i++) { vals[i] = expf(vals[i] - mx); sum += vals[i]; }
            #pragma unroll
            for (int o = 16; o > 0; o >>= 1) sum += __shfl_xor_sync(0xffffffffu, sum, o);
            float inv = 1.0f / sum;
            #pragma unroll
            for (int i = 0; i < 16; i++) {
                float p = vals[i] * inv;
                aout[(size_t)r * SS + lane + 32 * i] = p;
                row[lane + 32 * i] = tf2f(p);
            }
        }
    }

    // ---- phase 3: ctx = P @ V (V streamed in 64-row chunks) ----
    const int wm3 = warp & 3;   // 4 warps over M (16 rows each)
    const int wn3 = warp >> 2;  // 2 warps over N (32 cols each)
    float cacc[4][4];
    #pragma unroll
    for (int j = 0; j < 4; j++)
        #pragma unroll
        for (int k = 0; k < 4; k++) cacc[j][k] = 0.f;

    const float* vsrcb = g_v + (size_t)bh * SS * DK;
    #pragma unroll 1
    for (int ch = 0; ch < 8; ch++) {
        __syncthreads();   // prior consumers of sQV done (also orders after softmax)
        #pragma unroll
        for (int it = 0; it < 4; it++) {
            int f = tid + 256 * it;
            int r = f >> 4, c = (f & 15) << 2;
            float4 v = *reinterpret_cast<const float4*>(vsrcb + (size_t)(ch * 64 + r) * DK + c);
            float* p = &sQV[r * 72 + c];
            p[0] = tf2f(v.x); p[1] = tf2f(v.y); p[2] = tf2f(v.z); p[3] = tf2f(v.w);
        }
        __syncthreads();
        #pragma unroll 1
        for (int kk = 0; kk < 64; kk += 8) {
            unsigned a[4];
            int rb = wm3 * 16 + gid;
            int col = ch * 64 + kk + tig;
            a[0] = __float_as_uint(sK[rb * 516 + col]);
            a[1] = __float_as_uint(sK[(rb + 8) * 516 + col]);
            a[2] = __float_as_uint(sK[rb * 516 + col + 4]);
            a[3] = __float_as_uint(sK[(rb + 8) * 516 + col + 4]);
            #pragma unroll
            for (int nf = 0; nf < 4; nf++) {
                int nb = wn3 * 32 + nf * 8 + gid;
                unsigned bb0 = __float_as_uint(sQV[(kk + tig) * 72 + nb]);
                unsigned bb1 = __float_as_uint(sQV[(kk + 4 + tig) * 72 + nb]);
                mma8(cacc[nf], a, bb0, bb1);
            }
        }
    }

    // write ctx tile -> g_ctx [m = b*S+s][h*64+d]
    #pragma unroll
    for (int rr = 0; rr < 2; rr++) {
        int s = q0 + wm3 * 16 + gid + rr * 8;
        #pragma unroll
        for (int nf = 0; nf < 4; nf++) {
            int d = wn3 * 32 + nf * 8 + tig * 2;
            *reinterpret_cast<float2*>(
                &g_ctx[((size_t)b * SS + s) * DD + h * DK + d]) =
                make_float2(cacc[nf][rr * 2], cacc[nf][rr * 2 + 1]);
        }
    }
}

// =====================================================================
// LayerNorm over rows of g_res -> y output
// =====================================================================
__global__ __launch_bounds__(256)
void ln_kernel(const float* __restrict__ ln_g, const float* __restrict__ ln_b,
               float* __restrict__ y_out)
{
    __shared__ float rs[8], rq[8];
    const int r = blockIdx.x, t = threadIdx.x;
    const float* row = g_res + (size_t)r * DD;
    float v[4], s = 0.f, q = 0.f;
    #pragma unroll
    for (int i = 0; i < 4; i++) { v[i] = row[t + 256 * i]; s += v[i]; q += v[i] * v[i]; }
    #pragma unroll
    for (int o = 16; o > 0; o >>= 1) {
        s += __shfl_xor_sync(0xffffffffu, s, o);
        q += __shfl_xor_sync(0xffffffffu, q, o);
    }
    if ((t & 31) == 0) { rs[t >> 5] = s; rq[t >> 5] = q; }
    __syncthreads();
    if (t < 32) {
        float ss = (t < 8) ? rs[t] : 0.f;
        float qq = (t < 8) ? rq[t] : 0.f;
        #pragma unroll
        for (int o = 4; o > 0; o >>= 1) {
            ss += __shfl_xor_sync(0xffffffffu, ss, o);
            qq += __shfl_xor_sync(0xffffffffu, qq, o);
        }
        if (t == 0) { rs[0] = ss; rq[0] = qq; }
    }
    __syncthreads();
    float mean = rs[0] * (1.0f / 1024.0f);
    float var  = rq[0] * (1.0f / 1024.0f) - mean * mean;
    float rstd = rsqrtf(var + 1e-5f);
    #pragma unroll
    for (int i = 0; i < 4; i++) {
        int c = t + 256 * i;
        y_out[(size_t)r * DD + c] = (v[i] - mean) * rstd * ln_g[c] + ln_b[c];
    }
}

// =====================================================================
extern "C" void kernel_launch(void* const* d_in, const int* in_sizes, int n_in,
                              void* d_out, int out_size)
{
    const float* x    = (const float*)d_in[0];
    const float* Wq   = (const float*)d_in[1];
    const float* bq   = (const float*)d_in[2];
    const float* Wk   = (const float*)d_in[3];
    const float* bk   = (const float*)d_in[4];
    const float* Wv   = (const float*)d_in[5];
    const float* bv   = (const float*)d_in[6];
    const float* Wo   = (const float*)d_in[7];
    const float* bo   = (const float*)d_in[8];
    const float* ln_g = (const float*)d_in[9];
    const float* ln_b = (const float*)d_in[10];
    const float* hv   = (const float*)d_in[11];
    const int*   hm   = (const int*)d_in[12];
    const int*   am   = (const int*)d_in[13];

    float* out = (float*)d_out;
    float* y_out    = out;                          // [B,S,D]
    float* attn_out = out + (size_t)MTOT * DD;      // [B,H,S,S]

    cudaFuncSetAttribute(attn_fused_kernel,
                         cudaFuncAttributeMaxDynamicSharedMemorySize, ATTN_SMEM_BYTES);

    // 1) QKV projections
    gemm_tf32_kernel<0><<<dim3(32, 16, 3), 256>>>(x, Wq, Wk, Wv, bq, bk, bv, nullptr);
    // 2) fused attention (scores + blend + softmax + attn write + ctx)
    attn_fused_kernel<<<dim3(BHTOT, 8), 256, ATTN_SMEM_BYTES>>>(hv, hm, am, attn_out);
    // 3) out projection + bias + residual
    gemm_tf32_kernel<1><<<dim3(32, 16, 1), 256>>>(x, Wo, Wo, Wo, bo, bo, bo, x);
    // 4) LayerNorm -> y
    ln_kernel<<<dim3(MTOT), 256>>>(ln_g, ln_b, y_out);
}

// round 4
// speedup vs baseline: 1.2071x; 1.2071x over previous
#include <cuda_runtime.h>
#include <cstdint>

#define NEG_INF_F (-1e9f)
#define HTHRESH_F (-1e8f)

// B=8, S=512, D=1024, H=16, DK=64
#define BB 8
#define SS 512
#define DD 1024
#define HH 16
#define DK 64
#define MTOT (BB*SS)          // 4096
#define BHTOT (BB*HH)         // 128

// -------- scratch (device globals; no cudaMalloc allowed) --------
__device__ float g_q[BB*HH*SS*DK];
__device__ float g_k[BB*HH*SS*DK];
__device__ float g_v[BB*HH*SS*DK];
__device__ float g_ctx[MTOT*DD];
__device__ float g_res[MTOT*DD];

// -------- helpers --------
__device__ __forceinline__ void mma8(float c[4], const unsigned a[4], unsigned b0, unsigned b1) {
    asm volatile(
        "mma.sync.aligned.m16n8k8.row.col.f32.tf32.tf32.f32 "
        "{%0,%1,%2,%3}, {%4,%5,%6,%7}, {%8,%9}, {%0,%1,%2,%3};\n"
        : "+f"(c[0]), "+f"(c[1]), "+f"(c[2]), "+f"(c[3])
        : "r"(a[0]), "r"(a[1]), "r"(a[2]), "r"(a[3]), "r"(b0), "r"(b1));
}
__device__ __forceinline__ void cp16(float* smem_dst, const float* gsrc) {
    unsigned d = (unsigned)__cvta_generic_to_shared(smem_dst);
    asm volatile("cp.async.cg.shared.global [%0], [%1], 16;\n" :: "r"(d), "l"(gsrc));
}
__device__ __forceinline__ void cp_commit() {
    asm volatile("cp.async.commit_group;\n");
}
template<int N>
__device__ __forceinline__ void cp_wait() {
    asm volatile("cp.async.wait_group %0;\n" :: "n"(N));
}

// =====================================================================
// GEMM: C[4096,1024] = A @ W (+bias [+residual])
// 128x128x32 tiles, 3-stage cp.async pipeline, XOR-swizzled smem.
// 256 threads = 8 warps in 2(M) x 4(N); warp tile 64x32.
// MODE 0: QKV (z selects W/bias/dst, scatter to [B,H,S,DK])
// MODE 1: out-proj + bias + residual -> g_res
// =====================================================================
#define GBM 128
#define GBN 128
#define GBK 32
#define GST 3
#define GEMM_SMEM_BYTES (GST * (GBM*GBK + GBK*GBN) * 4)   // 98304

template<int MODE>
__global__ __launch_bounds__(256)
void gemm_tf32_kernel(const float* __restrict__ Aparam,
                      const float* __restrict__ W0, const float* __restrict__ W1,
                      const float* __restrict__ W2,
                      const float* __restrict__ bias0, const float* __restrict__ bias1,
                      const float* __restrict__ bias2,
                      const float* __restrict__ xres)
{
    extern __shared__ float gsm[];
    float* sA = gsm;                       // [GST][128*32]
    float* sB = gsm + GST * (GBM * GBK);   // [GST][32*128]

    const int z = blockIdx.z;
    const float* W    = (z == 0) ? W0 : (z == 1 ? W1 : W2);
    const float* bias = (z == 0) ? bias0 : (z == 1 ? bias1 : bias2);
    const float* A    = (MODE == 0) ? Aparam : g_ctx;
    float* dst;
    if (MODE == 0) dst = (z == 0) ? g_q : (z == 1 ? g_k : g_v);
    else           dst = g_res;

    const int m0 = blockIdx.x * GBM;
    const int n0 = blockIdx.y * GBN;
    const int tid = threadIdx.x;
    const int warp = tid >> 5, lane = tid & 31, gid = lane >> 2, tig = lane & 3;
    const int wm = warp & 1, wn = warp >> 1;    // 2 x 4 warp grid; warp tile 64x32

    float acc[4][4][4];
    #pragma unroll
    for (int i = 0; i < 4; i++)
        #pragma unroll
        for (int j = 0; j < 4; j++)
            #pragma unroll
            for (int k = 0; k < 4; k++) acc[i][j][k] = 0.f;

    // ---- tile loader (cp.async, swizzled) ----
    auto load_tile = [&](int st, int kt) {
        float* dA = sA + st * (GBM * GBK);
        float* dB = sB + st * (GBK * GBN);
        #pragma unroll
        for (int j = 0; j < 4; j++) {            // A: 128 rows x 8 chunks
            int idx = tid + 256 * j;
            int r = idx >> 3, c = idx & 7;
            cp16(dA + r * 32 + ((c ^ (r & 7)) << 2),
                 A + (size_t)(m0 + r) * DD + kt + (c << 2));
        }
        #pragma unroll
        for (int j = 0; j < 4; j++) {            // B: 32 rows x 32 chunks
            int idx = tid + 256 * j;
            int r = idx >> 5, c = idx & 31;
            cp16(dB + r * 128 + ((c ^ (r & 7)) << 2),
                 W + (size_t)(kt + r) * DD + n0 + (c << 2));
        }
    };

    // prologue: stages 0..GST-2
    #pragma unroll
    for (int s = 0; s < GST - 1; s++) { load_tile(s, s * GBK); cp_commit(); }

    const int NIT = DD / GBK;   // 32
    for (int it = 0; it < NIT; it++) {
        cp_wait<GST - 2>();
        __syncthreads();
        int nxt = it + GST - 1;
        if (nxt < NIT) load_tile(nxt % GST, nxt * GBK);
        cp_commit();

        const float* tA = sA + (it % GST) * (GBM * GBK);
        const float* tB = sB + (it % GST) * (GBK * GBN);
        #pragma unroll
        for (int kk = 0; kk < GBK; kk += 8) {
            unsigned a[4][4];
            const int c0 = kk >> 2;
            #pragma unroll
            for (int mf = 0; mf < 4; mf++) {
                int R = wm * 64 + mf * 16 + gid;     // R&7 == gid
                a[mf][0] = __float_as_uint(tA[R * 32 + ((c0 ^ gid) << 2) + tig]);
                a[mf][1] = __float_as_uint(tA[(R + 8) * 32 + ((c0 ^ gid) << 2) + tig]);
                a[mf][2] = __float_as_uint(tA[R * 32 + (((c0 + 1) ^ gid) << 2) + tig]);
                a[mf][3] = __float_as_uint(tA[(R + 8) * 32 + (((c0 + 1) ^ gid) << 2) + tig]);
            }
            #pragma unroll
            for (int nf = 0; nf < 4; nf++) {
                int nb = wn * 32 + nf * 8 + gid;
                int cc = nb >> 2, el = nb & 3;
                int k0 = kk + tig, k1 = kk + 4 + tig;
                unsigned b0 = __float_as_uint(tB[k0 * 128 + ((cc ^ (k0 & 7)) << 2) + el]);
                unsigned b1 = __float_as_uint(tB[k1 * 128 + ((cc ^ (k1 & 7)) << 2) + el]);
                #pragma unroll
                for (int mf = 0; mf < 4; mf++) mma8(acc[mf][nf], a[mf], b0, b1);
            }
        }
    }

    // epilogue
    #pragma unroll
    for (int mf = 0; mf < 4; mf++) {
        #pragma unroll
        for (int rr = 0; rr < 2; rr++) {
            int m = m0 + wm * 64 + mf * 16 + gid + rr * 8;
            #pragma unroll
            for (int nf = 0; nf < 4; nf++) {
                int n = n0 + wn * 32 + nf * 8 + tig * 2;
                float v0 = acc[mf][nf][rr * 2 + 0] + bias[n];
                float v1 = acc[mf][nf][rr * 2 + 1] + bias[n + 1];
                if (MODE == 0) {
                    int bidx = m >> 9, s = m & 511, hh = n >> 6, d = n & 63;
                    *reinterpret_cast<float2*>(
                        &dst[(((size_t)bidx * HH + hh) * SS + s) * DK + d]) = make_float2(v0, v1);
                } else {
                    v0 += xres[(size_t)m * DD + n];
                    v1 += xres[(size_t)m * DD + n + 1];
                    *reinterpret_cast<float2*>(&dst[(size_t)m * DD + n]) = make_float2(v0, v1);
                }
            }
        }
    }
}

// =====================================================================
// Fused attention kernel: block = (b,h, 64-row q-tile), 256 threads.
//   phase1: S = Q @ K^T * 0.125, masked + help-blended (K fully in smem)
//   phase2: row softmax in smem; write attn to gmem; P stays in smem
//   phase3: ctx = P @ V, V triple-buffered 64-row chunks (prefetched
//           during the softmax phase via cp.async)
// smem: sK 512x72 (reused as scores 64x516) + 3 x 64x72 buffers.
// =====================================================================
#define AST 72
#define SK_FLOATS (512 * AST)        // 36864
#define VB_FLOATS (64 * AST)         // 4608
#define ATTN_SMEM_BYTES ((SK_FLOATS + 3 * VB_FLOATS) * 4)   // 202752

__global__ __launch_bounds__(256)
void attn_fused_kernel(const float* __restrict__ help_vals,
                       const int* __restrict__ help_mask,
                       const int* __restrict__ amask,
                       float* __restrict__ attn_out)
{
    extern __shared__ float smem[];
    float* sK = smem;                               // K tile / scores (stride 516)
    float* vb0 = smem + SK_FLOATS;                  // Q, then V chunks
    float* vb1 = vb0 + VB_FLOATS;
    float* vb2 = vb1 + VB_FLOATS;

    const int bh = blockIdx.x;
    const int b = bh >> 4;
    const int h = bh & 15;
    const int q0 = blockIdx.y * 64;
    const int tid = threadIdx.x;
    const int warp = tid >> 5, lane = tid & 31, gid = lane >> 2, tig = lane & 3;

    const float* vsrcb = g_v + (size_t)bh * SS * DK;

    // ---- async load Q tile (into vb0) and full K ----
    {
        const float* qsrc = g_q + ((size_t)bh * SS + q0) * DK;
        #pragma unroll
        for (int j = 0; j < 4; j++) {
            int idx = tid + 256 * j;
            int r = idx >> 4, c = (idx & 15) << 2;
            cp16(vb0 + r * AST + c, qsrc + r * DK + c);
        }
        const float* ksrc = g_k + (size_t)bh * SS * DK;
        #pragma unroll
        for (int j = 0; j < 32; j++) {
            int idx = tid + 256 * j;
            int r = idx >> 4, c = (idx & 15) << 2;
            cp16(sK + r * AST + c, ksrc + r * DK + c);
        }
        cp_commit();
        cp_wait<0>();
        __syncthreads();
    }

    // ---- phase 1: scores = Q @ K^T ----
    const int wm = warp & 1;   // 2 warps over M (32 rows)
    const int wn = warp >> 1;  // 4 warps over N (128 cols)
    float acc[2][16][4];
    #pragma unroll
    for (int i = 0; i < 2; i++)
        #pragma unroll
        for (int j = 0; j < 16; j++)
            #pragma unroll
            for (int k = 0; k < 4; k++) acc[i][j][k] = 0.f;

    #pragma unroll 1
    for (int kk = 0; kk < DK; kk += 8) {
        unsigned a[2][4];
        #pragma unroll
        for (int mf = 0; mf < 2; mf++) {
            int rb = wm * 32 + mf * 16 + gid;
            a[mf][0] = __float_as_uint(vb0[rb * AST + kk + tig]);
            a[mf][1] = __float_as_uint(vb0[(rb + 8) * AST + kk + tig]);
            a[mf][2] = __float_as_uint(vb0[rb * AST + kk + 4 + tig]);
            a[mf][3] = __float_as_uint(vb0[(rb + 8) * AST + kk + 4 + tig]);
        }
        #pragma unroll
        for (int nf = 0; nf < 16; nf++) {
            int nb = wn * 128 + nf * 8 + gid;
            unsigned bb0 = __float_as_uint(sK[nb * AST + kk + tig]);
            unsigned bb1 = __float_as_uint(sK[nb * AST + kk + 4 + tig]);
            mma8(acc[0][nf], a[0], bb0, bb1);
            mma8(acc[1][nf], a[1], bb0, bb1);
        }
    }
    __syncthreads();   // K/Q dead; overlay scores on sK

    // prefetch V chunks 0,1 (land during blend + softmax)
    {
        #pragma unroll
        for (int j = 0; j < 4; j++) {
            int idx = tid + 256 * j;
            int r = idx >> 4, c = (idx & 15) << 2;
            cp16(vb1 + r * AST + c, vsrcb + r * DK + c);
        }
        cp_commit();
        #pragma unroll
        for (int j = 0; j < 4; j++) {
            int idx = tid + 256 * j;
            int r = idx >> 4, c = (idx & 15) << 2;
            cp16(vb2 + r * AST + c, vsrcb + (64 + r) * DK + c);
        }
        cp_commit();
    }

    // ---- score epilogue: scale + attn_mask + dependency blend -> sK ----
    {
        const float* hvp = help_vals + ((size_t)bh * SS + q0) * SS;
        const int*   hmp = help_mask + ((size_t)bh * SS + q0) * SS;
        const int*   amp = amask + ((size_t)b * SS + q0) * SS;
        #pragma unroll
        for (int mf = 0; mf < 2; mf++) {
            #pragma unroll
            for (int rr = 0; rr < 2; rr++) {
                int lm = wm * 32 + mf * 16 + gid + rr * 8;
                #pragma unroll
                for (int nf = 0; nf < 16; nf++) {
                    int ln = wn * 128 + nf * 8 + tig * 2;
                    size_t off = (size_t)lm * SS + ln;
                    float2 hv2 = *reinterpret_cast<const float2*>(hvp + off);
                    int2   hm2 = *reinterpret_cast<const int2*>(hmp + off);
                    int2   am2 = *reinterpret_cast<const int2*>(amp + off);
                    float s0 = am2.x ? NEG_INF_F : acc[0 + mf][nf][rr * 2 + 0] * 0.125f;
                    float s1 = am2.x ? 0.f : 0.f;  // placeholder (overwritten below)
                    s0 = am2.x ? NEG_INF_F : acc[mf][nf][rr * 2 + 0] * 0.125f;
                    s1 = am2.y ? NEG_INF_F : acc[mf][nf][rr * 2 + 1] * 0.125f;
                    if (hm2.x && hv2.x > HTHRESH_F) s0 = 0.5f * hv2.x + 0.5f * s0;
                    if (hm2.y && hv2.y > HTHRESH_F) s1 = 0.5f * hv2.y + 0.5f * s1;
                    sK[lm * 516 + ln]     = s0;
                    sK[lm * 516 + ln + 1] = s1;
                }
            }
        }
    }
    __syncthreads();

    // ---- phase 2: softmax per row; write attn to gmem; P stays in sK ----
    {
        float* aout = attn_out + ((size_t)bh * SS + q0) * SS;
        #pragma unroll 1
        for (int j = 0; j < 8; j++) {
            int r = warp * 8 + j;
            float* row = &sK[r * 516];
            float vals[16];
            float mx = -3e38f;
            #pragma unroll
            for (int i = 0; i < 16; i++) { vals[i] = row[lane + 32 * i]; mx = fmaxf(mx, vals[i]); }
            #pragma unroll
            for (int o = 16; o > 0; o >>= 1) mx = fmaxf(mx, __shfl_xor_sync(0xffffffffu, mx, o));
            float sum = 0.f;
            #pragma unroll
            for (int i = 0; i < 16; i++) { vals[i] = __expf(vals[i] - mx); sum += vals[i]; }
            #pragma unroll
            for (int o = 16; o > 0; o >>= 1) sum += __shfl_xor_sync(0xffffffffu, sum, o);
            float inv = 1.0f / sum;
            #pragma unroll
            for (int i = 0; i < 16; i++) {
                float p = vals[i] * inv;
                aout[(size_t)r * SS + lane + 32 * i] = p;
                row[lane + 32 * i] = p;
            }
        }
    }

    // ---- phase 3: ctx = P @ V, triple-buffered V chunks ----
    const int wm3 = warp & 3;   // 4 warps over M (16 rows)
    const int wn3 = warp >> 2;  // 2 warps over N (32 cols)
    float cacc[4][4];
    #pragma unroll
    for (int j = 0; j < 4; j++)
        #pragma unroll
        for (int k = 0; k < 4; k++) cacc[j][k] = 0.f;

    float* vbuf[3] = {vb0, vb1, vb2};
    #pragma unroll 1
    for (int ch = 0; ch < 8; ch++) {
        cp_wait<1>();
        __syncthreads();   // chunk ch ready; buffer (ch+2)%3 consumed
        if (ch + 2 < 8) {
            float* dstb = vbuf[(ch + 3) % 3];
            const float* src = vsrcb + (size_t)(ch + 2) * 64 * DK;
            #pragma unroll
            for (int j = 0; j < 4; j++) {
                int idx = tid + 256 * j;
                int r = idx >> 4, c = (idx & 15) << 2;
                cp16(dstb + r * AST + c, src + r * DK + c);
            }
        }
        cp_commit();

        const float* sV = vbuf[(ch + 1) % 3];
        #pragma unroll 1
        for (int kk = 0; kk < 64; kk += 8) {
            unsigned a[4];
            int rb = wm3 * 16 + gid;
            int col = ch * 64 + kk + tig;
            a[0] = __float_as_uint(sK[rb * 516 + col]);
            a[1] = __float_as_uint(sK[(rb + 8) * 516 + col]);
            a[2] = __float_as_uint(sK[rb * 516 + col + 4]);
            a[3] = __float_as_uint(sK[(rb + 8) * 516 + col + 4]);
            #pragma unroll
            for (int nf = 0; nf < 4; nf++) {
                int nb = wn3 * 32 + nf * 8 + gid;
                unsigned bb0 = __float_as_uint(sV[(kk + tig) * AST + nb]);
                unsigned bb1 = __float_as_uint(sV[(kk + 4 + tig) * AST + nb]);
                mma8(cacc[nf], a, bb0, bb1);
            }
        }
    }

    // write ctx tile -> g_ctx [m = b*S+s][h*64+d]
    #pragma unroll
    for (int rr = 0; rr < 2; rr++) {
        int s = q0 + wm3 * 16 + gid + rr * 8;
        #pragma unroll
        for (int nf = 0; nf < 4; nf++) {
            int d = wn3 * 32 + nf * 8 + tig * 2;
            *reinterpret_cast<float2*>(
                &g_ctx[((size_t)b * SS + s) * DD + h * DK + d]) =
                make_float2(cacc[nf][rr * 2], cacc[nf][rr * 2 + 1]);
        }
    }
}

// =====================================================================
// LayerNorm over rows of g_res -> y output (float4 loads, 1 row/block)
// =====================================================================
__global__ __launch_bounds__(256)
void ln_kernel(const float* __restrict__ ln_g, const float* __restrict__ ln_b,
               float* __restrict__ y_out)
{
    __shared__ float rs[8], rq[8];
    const int r = blockIdx.x, t = threadIdx.x;
    const float4* row4 = reinterpret_cast<const float4*>(g_res + (size_t)r * DD);
    float4 v = row4[t];
    float s = v.x + v.y + v.z + v.w;
    float q = v.x * v.x + v.y * v.y + v.z * v.z + v.w * v.w;
    #pragma unroll
    for (int o = 16; o > 0; o >>= 1) {
        s += __shfl_xor_sync(0xffffffffu, s, o);
        q += __shfl_xor_sync(0xffffffffu, q, o);
    }
    if ((t & 31) == 0) { rs[t >> 5] = s; rq[t >> 5] = q; }
    __syncthreads();
    if (t < 32) {
        float ss = (t < 8) ? rs[t] : 0.f;
        float qq = (t < 8) ? rq[t] : 0.f;
        #pragma unroll
        for (int o = 4; o > 0; o >>= 1) {
            ss += __shfl_xor_sync(0xffffffffu, ss, o);
            qq += __shfl_xor_sync(0xffffffffu, qq, o);
        }
        if (t == 0) { rs[0] = ss; rq[0] = qq; }
    }
    __syncthreads();
    float mean = rs[0] * (1.0f / 1024.0f);
    float var  = rq[0] * (1.0f / 1024.0f) - mean * mean;
    float rstd = rsqrtf(var + 1e-5f);
    const float4 g4 = reinterpret_cast<const float4*>(ln_g)[t];
    const float4 b4 = reinterpret_cast<const float4*>(ln_b)[t];
    float4 o;
    o.x = (v.x - mean) * rstd * g4.x + b4.x;
    o.y = (v.y - mean) * rstd * g4.y + b4.y;
    o.z = (v.z - mean) * rstd * g4.z + b4.z;
    o.w = (v.w - mean) * rstd * g4.w + b4.w;
    reinterpret_cast<float4*>(y_out + (size_t)r * DD)[t] = o;
}

// =====================================================================
extern "C" void kernel_launch(void* const* d_in, const int* in_sizes, int n_in,
                              void* d_out, int out_size)
{
    const float* x    = (const float*)d_in[0];
    const float* Wq   = (const float*)d_in[1];
    const float* bq   = (const float*)d_in[2];
    const float* Wk   = (const float*)d_in[3];
    const float* bk   = (const float*)d_in[4];
    const float* Wv   = (const float*)d_in[5];
    const float* bv   = (const float*)d_in[6];
    const float* Wo   = (const float*)d_in[7];
    const float* bo   = (const float*)d_in[8];
    const float* ln_g = (const float*)d_in[9];
    const float* ln_b = (const float*)d_in[10];
    const float* hv   = (const float*)d_in[11];
    const int*   hm   = (const int*)d_in[12];
    const int*   am   = (const int*)d_in[13];

    float* out = (float*)d_out;
    float* y_out    = out;                          // [B,S,D]
    float* attn_out = out + (size_t)MTOT * DD;      // [B,H,S,S]

    cudaFuncSetAttribute(gemm_tf32_kernel<0>,
                         cudaFuncAttributeMaxDynamicSharedMemorySize, GEMM_SMEM_BYTES);
    cudaFuncSetAttribute(gemm_tf32_kernel<1>,
                         cudaFuncAttributeMaxDynamicSharedMemorySize, GEMM_SMEM_BYTES);
    cudaFuncSetAttribute(attn_fused_kernel,
                         cudaFuncAttributeMaxDynamicSharedMemorySize, ATTN_SMEM_BYTES);

    // 1) QKV projections
    gemm_tf32_kernel<0><<<dim3(32, 8, 3), 256, GEMM_SMEM_BYTES>>>(
        x, Wq, Wk, Wv, bq, bk, bv, nullptr);
    // 2) fused attention (scores + blend + softmax + attn write + ctx)
    attn_fused_kernel<<<dim3(BHTOT, 8), 256, ATTN_SMEM_BYTES>>>(hv, hm, am, attn_out);
    // 3) out projection + bias + residual
    gemm_tf32_kernel<1><<<dim3(32, 8, 1), 256, GEMM_SMEM_BYTES>>>(
        x, Wo, Wo, Wo, bo, bo, bo, x);
    // 4) LayerNorm -> y
    ln_kernel<<<dim3(MTOT), 256>>>(ln_g, ln_b, y_out);
}